// round 1
// baseline (speedup 1.0000x reference)
#include <cuda_runtime.h>
#include <math.h>

#define NB 8192
#define NSLICE 8
#define JPS (NB / NSLICE)  // 1024
#define LOG2E 1.4426950408889634f

// ---- scratch (device globals; no allocation allowed) ----
__device__ float4 gX[NB];          // x after MLP chain [B,4]
__device__ float4 gQ[NB];          // q * (0.5 * log2e)  (folds softmax scale + exp2 conversion)
__device__ float4 gK[NB];          // k
__device__ float  gQn[NB];         // |q_tilde|
__device__ unsigned gKmaxBits;     // max_j |k_j| as float bits (positive floats order-preserve)
__device__ float  gPsum[NSLICE * NB];
__device__ float4 gPacc[NSLICE * NB];

__device__ __forceinline__ float ex2f(float x) {
    float y;
    asm("ex2.approx.ftz.f32 %0, %1;" : "=f"(y) : "f"(x));
    return y;
}

__global__ void k_init() { gKmaxBits = 0u; }

// ---------- Kernel A: MLP chain + q,k projection (thread per row) ----------
__global__ void k_prep(const float* __restrict__ inp,
                       const float* __restrict__ Wfm, const float* __restrict__ bfm,
                       const float* __restrict__ Wc1, const float* __restrict__ bc1,
                       const float* __restrict__ Wp1, const float* __restrict__ bp1,
                       const float* __restrict__ Wc2, const float* __restrict__ bc2,
                       const float* __restrict__ Wp2, const float* __restrict__ bp2,
                       const float* __restrict__ Wc3, const float* __restrict__ bc3,
                       const float* __restrict__ rot, const float* __restrict__ ent)
{
    int r = blockIdx.x * blockDim.x + threadIdx.x;
    if (r >= NB) return;

    float in0[8];
    #pragma unroll
    for (int i = 0; i < 8; i++) in0[i] = inp[r * 8 + i];

    float a[16], h[16];
    // fm: 8 -> 16
    #pragma unroll
    for (int o = 0; o < 16; o++) {
        float s = bfm[o];
        #pragma unroll
        for (int i = 0; i < 8; i++) s = fmaf(in0[i], Wfm[i * 16 + o], s);
        a[o] = tanhf(s);
    }
    // c1: 16 -> 16
    #pragma unroll
    for (int o = 0; o < 16; o++) {
        float s = bc1[o];
        #pragma unroll
        for (int i = 0; i < 16; i++) s = fmaf(a[i], Wc1[i * 16 + o], s);
        h[o] = tanhf(s);
    }
    // p1: 16 -> 12
    #pragma unroll
    for (int o = 0; o < 12; o++) {
        float s = bp1[o];
        #pragma unroll
        for (int i = 0; i < 16; i++) s = fmaf(h[i], Wp1[i * 12 + o], s);
        a[o] = tanhf(s);
    }
    // c2: 12 -> 8
    #pragma unroll
    for (int o = 0; o < 8; o++) {
        float s = bc2[o];
        #pragma unroll
        for (int i = 0; i < 12; i++) s = fmaf(a[i], Wc2[i * 8 + o], s);
        h[o] = tanhf(s);
    }
    // p2: 8 -> 4
    #pragma unroll
    for (int o = 0; o < 4; o++) {
        float s = bp2[o];
        #pragma unroll
        for (int i = 0; i < 8; i++) s = fmaf(h[i], Wp2[i * 4 + o], s);
        a[o] = tanhf(s);
    }
    // c3: 4 -> 4
    #pragma unroll
    for (int o = 0; o < 4; o++) {
        float s = bc3[o];
        #pragma unroll
        for (int i = 0; i < 4; i++) s = fmaf(a[i], Wc3[i * 4 + o], s);
        h[o] = tanhf(s);
    }

    float4 x = make_float4(h[0], h[1], h[2], h[3]);

    // q_tilde = (x @ rot) * 0.5 * log2e ;  k = x @ ent
    float q[4], k[4];
    #pragma unroll
    for (int c = 0; c < 4; c++) {
        float sq = 0.f, sk = 0.f;
        #pragma unroll
        for (int i = 0; i < 4; i++) {
            sq = fmaf(h[i], rot[i * 4 + c], sq);
            sk = fmaf(h[i], ent[i * 4 + c], sk);
        }
        q[c] = sq * (0.5f * LOG2E);
        k[c] = sk;
    }

    gX[r] = x;
    gQ[r] = make_float4(q[0], q[1], q[2], q[3]);
    gK[r] = make_float4(k[0], k[1], k[2], k[3]);

    float qn = sqrtf(q[0]*q[0] + q[1]*q[1] + q[2]*q[2] + q[3]*q[3]);
    gQn[r] = qn;
    float kn = sqrtf(k[0]*k[0] + k[1]*k[1] + k[2]*k[2] + k[3]*k[3]);
    atomicMax(&gKmaxBits, __float_as_uint(kn));
}

// ---------- Kernel B: streaming attention (thread = row, blockIdx.y = j-slice) ----------
// softmax shift-invariance: subtract per-row constant m = |q_tilde| * max|k| (>= every
// score by Cauchy-Schwarz) -> exp2 args <= 0, and partial (sum, acc) over j-slices
// combine by plain addition (exact cancellation of the offset in acc/sum).
__global__ void __launch_bounds__(256) k_attn() {
    int row   = blockIdx.x * 256 + threadIdx.x;
    int slice = blockIdx.y;

    float4 q = gQ[row];
    float  m = gQn[row] * __uint_as_float(gKmaxBits);
    float  negm = -m;

    float  sum = 0.f;
    float4 acc = make_float4(0.f, 0.f, 0.f, 0.f);

    const float4* __restrict__ kp = gK;
    const float4* __restrict__ xp = gX;

    int j0 = slice * JPS;
    #pragma unroll 8
    for (int j = j0; j < j0 + JPS; j++) {
        float4 kj = __ldg(kp + j);
        float4 xj = __ldg(xp + j);
        float s = fmaf(q.x, kj.x,
                  fmaf(q.y, kj.y,
                  fmaf(q.z, kj.z,
                  fmaf(q.w, kj.w, negm))));
        float e = ex2f(s);
        sum += e;
        acc.x = fmaf(e, xj.x, acc.x);
        acc.y = fmaf(e, xj.y, acc.y);
        acc.z = fmaf(e, xj.z, acc.z);
        acc.w = fmaf(e, xj.w, acc.w);
    }

    gPsum[slice * NB + row] = sum;
    gPacc[slice * NB + row] = acc;
}

// ---------- Kernel C: reduce slices + conv-sigmoid + head-sigmoid ----------
__global__ void k_tail(const float* __restrict__ conv_w, const float* __restrict__ conv_b,
                       const float* __restrict__ head_w, const float* __restrict__ head_b,
                       float* __restrict__ out)
{
    int row = blockIdx.x * blockDim.x + threadIdx.x;
    if (row >= NB) return;

    float sum = 0.f;
    float4 acc = make_float4(0.f, 0.f, 0.f, 0.f);
    #pragma unroll
    for (int s = 0; s < NSLICE; s++) {
        sum += gPsum[s * NB + row];
        float4 p = gPacc[s * NB + row];
        acc.x += p.x; acc.y += p.y; acc.z += p.z; acc.w += p.w;
    }
    float inv = 1.f / sum;
    float ax = acc.x * inv, ay = acc.y * inv, az = acc.z * inv, aw = acc.w * inv;

    float z = fmaf(ax, conv_w[0], fmaf(ay, conv_w[1],
              fmaf(az, conv_w[2], fmaf(aw, conv_w[3], conv_b[0]))));
    float f = 1.f / (1.f + expf(-z));
    float logit = fmaf(f, head_w[0], head_b[0]);
    out[row] = 1.f / (1.f + expf(-logit));
}

extern "C" void kernel_launch(void* const* d_in, const int* in_sizes, int n_in,
                              void* d_out, int out_size)
{
    const float* inp  = (const float*)d_in[0];
    const float* Wfm  = (const float*)d_in[1];
    const float* bfm  = (const float*)d_in[2];
    const float* Wc1  = (const float*)d_in[3];
    const float* bc1  = (const float*)d_in[4];
    const float* Wp1  = (const float*)d_in[5];
    const float* bp1  = (const float*)d_in[6];
    const float* Wc2  = (const float*)d_in[7];
    const float* bc2  = (const float*)d_in[8];
    const float* Wp2  = (const float*)d_in[9];
    const float* bp2  = (const float*)d_in[10];
    const float* Wc3  = (const float*)d_in[11];
    const float* bc3  = (const float*)d_in[12];
    const float* rot  = (const float*)d_in[13];
    const float* ent  = (const float*)d_in[14];
    const float* cw   = (const float*)d_in[15];
    const float* cb   = (const float*)d_in[16];
    const float* hw   = (const float*)d_in[17];
    const float* hb   = (const float*)d_in[18];
    float* out = (float*)d_out;

    k_init<<<1, 1>>>();
    k_prep<<<NB / 256, 256>>>(inp, Wfm, bfm, Wc1, bc1, Wp1, bp1,
                              Wc2, bc2, Wp2, bp2, Wc3, bc3, rot, ent);
    dim3 gridB(NB / 256, NSLICE);
    k_attn<<<gridB, 256>>>();
    k_tail<<<NB / 256, 256>>>(cw, cb, hw, hb, out);
}

// round 2
// speedup vs baseline: 1.9809x; 1.9809x over previous
#include <cuda_runtime.h>
#include <math.h>

#define NB 8192
#define NSLICE 16
#define JPS (NB / NSLICE)          // 512
#define RPT 4                      // rows per thread in attention
#define RSTRIDE (NB / RPT)         // 2048
#define LOG2E 1.4426950408889634f

// ---- scratch (device globals; no allocation allowed) ----
__device__ float4 gQ[NB];          // q * (0.5 * log2e)  (folds softmax scale + exp2 conversion)
__device__ float4 gK[NB];          // k
__device__ float  gC[NB];          // c_j = x_j . conv_w  (conv folded into attention)
__device__ float  gQn[NB];         // |q_tilde|
__device__ unsigned gKmaxBits;     // max_j |k_j| as float bits (positive floats order-preserve)
__device__ float  gPsum[NSLICE * NB];
__device__ float  gPy[NSLICE * NB];

__device__ __forceinline__ float ex2f(float x) {
    float y;
    asm("ex2.approx.ftz.f32 %0, %1;" : "=f"(y) : "f"(x));
    return y;
}

__global__ void k_init() { gKmaxBits = 0u; }

// ---------- Kernel A: MLP chain + q,k projection + conv scalar ----------
__global__ void k_prep(const float* __restrict__ inp,
                       const float* __restrict__ Wfm, const float* __restrict__ bfm,
                       const float* __restrict__ Wc1, const float* __restrict__ bc1,
                       const float* __restrict__ Wp1, const float* __restrict__ bp1,
                       const float* __restrict__ Wc2, const float* __restrict__ bc2,
                       const float* __restrict__ Wp2, const float* __restrict__ bp2,
                       const float* __restrict__ Wc3, const float* __restrict__ bc3,
                       const float* __restrict__ rot, const float* __restrict__ ent,
                       const float* __restrict__ conv_w)
{
    int r = blockIdx.x * blockDim.x + threadIdx.x;
    if (r >= NB) return;

    float in0[8];
    #pragma unroll
    for (int i = 0; i < 8; i++) in0[i] = inp[r * 8 + i];

    float a[16], h[16];
    #pragma unroll
    for (int o = 0; o < 16; o++) {
        float s = bfm[o];
        #pragma unroll
        for (int i = 0; i < 8; i++) s = fmaf(in0[i], Wfm[i * 16 + o], s);
        a[o] = tanhf(s);
    }
    #pragma unroll
    for (int o = 0; o < 16; o++) {
        float s = bc1[o];
        #pragma unroll
        for (int i = 0; i < 16; i++) s = fmaf(a[i], Wc1[i * 16 + o], s);
        h[o] = tanhf(s);
    }
    #pragma unroll
    for (int o = 0; o < 12; o++) {
        float s = bp1[o];
        #pragma unroll
        for (int i = 0; i < 16; i++) s = fmaf(h[i], Wp1[i * 12 + o], s);
        a[o] = tanhf(s);
    }
    #pragma unroll
    for (int o = 0; o < 8; o++) {
        float s = bc2[o];
        #pragma unroll
        for (int i = 0; i < 12; i++) s = fmaf(a[i], Wc2[i * 8 + o], s);
        h[o] = tanhf(s);
    }
    #pragma unroll
    for (int o = 0; o < 4; o++) {
        float s = bp2[o];
        #pragma unroll
        for (int i = 0; i < 8; i++) s = fmaf(h[i], Wp2[i * 4 + o], s);
        a[o] = tanhf(s);
    }
    #pragma unroll
    for (int o = 0; o < 4; o++) {
        float s = bc3[o];
        #pragma unroll
        for (int i = 0; i < 4; i++) s = fmaf(a[i], Wc3[i * 4 + o], s);
        h[o] = tanhf(s);
    }

    // q_tilde = (x @ rot) * 0.5 * log2e ;  k = x @ ent
    float q[4], k[4];
    #pragma unroll
    for (int c = 0; c < 4; c++) {
        float sq = 0.f, sk = 0.f;
        #pragma unroll
        for (int i = 0; i < 4; i++) {
            sq = fmaf(h[i], rot[i * 4 + c], sq);
            sk = fmaf(h[i], ent[i * 4 + c], sk);
        }
        q[c] = sq * (0.5f * LOG2E);
        k[c] = sk;
    }

    gQ[r] = make_float4(q[0], q[1], q[2], q[3]);
    gK[r] = make_float4(k[0], k[1], k[2], k[3]);
    // conv folded: scalar projection of x onto conv_w
    gC[r] = fmaf(h[0], conv_w[0], fmaf(h[1], conv_w[1],
            fmaf(h[2], conv_w[2], h[3] * conv_w[3])));

    float qn = sqrtf(q[0]*q[0] + q[1]*q[1] + q[2]*q[2] + q[3]*q[3]);
    gQn[r] = qn;
    float kn = sqrtf(k[0]*k[0] + k[1]*k[1] + k[2]*k[2] + k[3]*k[3]);
    atomicMax(&gKmaxBits, __float_as_uint(kn));
}

// ---------- Kernel B: streaming attention, RPT rows/thread, conv-folded ----------
// exp2 args <= 0 via per-row Cauchy-Schwarz bound; slice partials (sum, y)
// combine by plain addition (row-constant offset cancels exactly in y/sum).
__global__ void __launch_bounds__(256) k_attn() {
    int t     = blockIdx.x * 256 + threadIdx.x;   // 0..RSTRIDE-1
    int slice = blockIdx.y;

    float kmax = __uint_as_float(gKmaxBits);

    float4 q[RPT];
    float  negm[RPT], sum[RPT], y[RPT];
    #pragma unroll
    for (int r = 0; r < RPT; r++) {
        int row = t + r * RSTRIDE;
        q[r]    = gQ[row];
        negm[r] = -gQn[row] * kmax;
        sum[r]  = 0.f;
        y[r]    = 0.f;
    }

    const float4* __restrict__ kp = gK;
    const float*  __restrict__ cp = gC;

    int j0 = slice * JPS;
    #pragma unroll 4
    for (int j = j0; j < j0 + JPS; j++) {
        float4 kj = __ldg(kp + j);
        float  cj = __ldg(cp + j);
        #pragma unroll
        for (int r = 0; r < RPT; r++) {
            float s = fmaf(q[r].x, kj.x,
                      fmaf(q[r].y, kj.y,
                      fmaf(q[r].z, kj.z,
                      fmaf(q[r].w, kj.w, negm[r]))));
            float e = ex2f(s);
            sum[r] += e;
            y[r]    = fmaf(e, cj, y[r]);
        }
    }

    #pragma unroll
    for (int r = 0; r < RPT; r++) {
        int row = t + r * RSTRIDE;
        gPsum[slice * NB + row] = sum[r];
        gPy[slice * NB + row]   = y[r];
    }
}

// ---------- Kernel C: reduce slices + conv-sigmoid + head-sigmoid ----------
__global__ void k_tail(const float* __restrict__ conv_b,
                       const float* __restrict__ head_w, const float* __restrict__ head_b,
                       float* __restrict__ out)
{
    int row = blockIdx.x * blockDim.x + threadIdx.x;
    if (row >= NB) return;

    float sum = 0.f, y = 0.f;
    #pragma unroll
    for (int s = 0; s < NSLICE; s++) {
        sum += gPsum[s * NB + row];
        y   += gPy[s * NB + row];
    }
    float z = fmaf(y, 1.f / sum, conv_b[0]);
    float f = 1.f / (1.f + expf(-z));
    float logit = fmaf(f, head_w[0], head_b[0]);
    out[row] = 1.f / (1.f + expf(-logit));
}

extern "C" void kernel_launch(void* const* d_in, const int* in_sizes, int n_in,
                              void* d_out, int out_size)
{
    const float* inp  = (const float*)d_in[0];
    const float* Wfm  = (const float*)d_in[1];
    const float* bfm  = (const float*)d_in[2];
    const float* Wc1  = (const float*)d_in[3];
    const float* bc1  = (const float*)d_in[4];
    const float* Wp1  = (const float*)d_in[5];
    const float* bp1  = (const float*)d_in[6];
    const float* Wc2  = (const float*)d_in[7];
    const float* bc2  = (const float*)d_in[8];
    const float* Wp2  = (const float*)d_in[9];
    const float* bp2  = (const float*)d_in[10];
    const float* Wc3  = (const float*)d_in[11];
    const float* bc3  = (const float*)d_in[12];
    const float* rot  = (const float*)d_in[13];
    const float* ent  = (const float*)d_in[14];
    const float* cw   = (const float*)d_in[15];
    const float* cb   = (const float*)d_in[16];
    const float* hw   = (const float*)d_in[17];
    const float* hb   = (const float*)d_in[18];
    float* out = (float*)d_out;

    k_init<<<1, 1>>>();
    k_prep<<<NB / 128, 128>>>(inp, Wfm, bfm, Wc1, bc1, Wp1, bp1,
                              Wc2, bc2, Wp2, bp2, Wc3, bc3, rot, ent, cw);
    dim3 gridB(RSTRIDE / 256, NSLICE);
    k_attn<<<gridB, 256>>>();
    k_tail<<<NB / 256, 256>>>(cb, hw, hb, out);
}

// round 3
// speedup vs baseline: 2.5078x; 1.2660x over previous
#include <cuda_runtime.h>
#include <math.h>

#define NB 8192
#define NSLICE 32
#define JPS (NB / NSLICE)      // 256
#define RPT 8                  // rows per thread in attention
#define RSTRIDE (NB / RPT)     // 1024
#define NPAIR (RPT / 2)        // 4 packed row-pairs
#define LOG2E 1.4426950408889634f

typedef unsigned long long u64;

// ---- scratch (device globals; no allocation allowed) ----
__device__ float4      gQ4[NB];       // q * (0.5*log2e) per row
__device__ float       gM[NB];        // -(|q_tilde| * kbound) per row
__device__ ulonglong2  gKDxy[NB];     // {pack(kx,kx), pack(ky,ky)}
__device__ ulonglong2  gKDzw[NB];     // {pack(kz,kz), pack(kw,kw)}
__device__ u64         gCCd[NB];      // pack(c,c), c = x . conv_w
__device__ float2      gP[NB * NSLICE]; // {sum, y} partials, slice-contiguous per row

__device__ __forceinline__ float ex2f(float x) {
    float y;
    asm("ex2.approx.ftz.f32 %0, %1;" : "=f"(y) : "f"(x));
    return y;
}
__device__ __forceinline__ u64 ffma2(u64 a, u64 b, u64 c) {
    u64 d;
    asm("fma.rn.f32x2 %0, %1, %2, %3;" : "=l"(d) : "l"(a), "l"(b), "l"(c));
    return d;
}
__device__ __forceinline__ u64 fadd2(u64 a, u64 b) {
    u64 d;
    asm("add.rn.f32x2 %0, %1, %2;" : "=l"(d) : "l"(a), "l"(b));
    return d;
}
__device__ __forceinline__ u64 pack2(float lo, float hi) {
    u64 d;
    asm("mov.b64 %0, {%1, %2};" : "=l"(d) : "f"(lo), "f"(hi));
    return d;
}
__device__ __forceinline__ void unpack2(u64 v, float& lo, float& hi) {
    asm("mov.b64 {%0, %1}, %2;" : "=f"(lo), "=f"(hi) : "l"(v));
}
// fast tanh via ex2 + approximate division: err ~1e-6, MUFU-pipe only
__device__ __forceinline__ float tanh_fast(float x) {
    float e = ex2f(x * (2.0f * LOG2E));
    return 1.0f - __fdividef(2.0f, e + 1.0f);
}

// ---------- Kernel A: MLP chain + q,k projection + conv scalar + row bound ----------
__global__ void k_prep(const float* __restrict__ inp,
                       const float* __restrict__ Wfm, const float* __restrict__ bfm,
                       const float* __restrict__ Wc1, const float* __restrict__ bc1,
                       const float* __restrict__ Wp1, const float* __restrict__ bp1,
                       const float* __restrict__ Wc2, const float* __restrict__ bc2,
                       const float* __restrict__ Wp2, const float* __restrict__ bp2,
                       const float* __restrict__ Wc3, const float* __restrict__ bc3,
                       const float* __restrict__ rot, const float* __restrict__ ent,
                       const float* __restrict__ conv_w)
{
    int r = blockIdx.x * blockDim.x + threadIdx.x;
    if (r >= NB) return;

    float in0[8];
    #pragma unroll
    for (int i = 0; i < 8; i++) in0[i] = inp[r * 8 + i];

    float a[16], h[16];
    #pragma unroll
    for (int o = 0; o < 16; o++) {
        float s = bfm[o];
        #pragma unroll
        for (int i = 0; i < 8; i++) s = fmaf(in0[i], Wfm[i * 16 + o], s);
        a[o] = tanh_fast(s);
    }
    #pragma unroll
    for (int o = 0; o < 16; o++) {
        float s = bc1[o];
        #pragma unroll
        for (int i = 0; i < 16; i++) s = fmaf(a[i], Wc1[i * 16 + o], s);
        h[o] = tanh_fast(s);
    }
    #pragma unroll
    for (int o = 0; o < 12; o++) {
        float s = bp1[o];
        #pragma unroll
        for (int i = 0; i < 16; i++) s = fmaf(h[i], Wp1[i * 12 + o], s);
        a[o] = tanh_fast(s);
    }
    #pragma unroll
    for (int o = 0; o < 8; o++) {
        float s = bc2[o];
        #pragma unroll
        for (int i = 0; i < 12; i++) s = fmaf(a[i], Wc2[i * 8 + o], s);
        h[o] = tanh_fast(s);
    }
    #pragma unroll
    for (int o = 0; o < 4; o++) {
        float s = bp2[o];
        #pragma unroll
        for (int i = 0; i < 8; i++) s = fmaf(h[i], Wp2[i * 4 + o], s);
        a[o] = tanh_fast(s);
    }
    #pragma unroll
    for (int o = 0; o < 4; o++) {
        float s = bc3[o];
        #pragma unroll
        for (int i = 0; i < 4; i++) s = fmaf(a[i], Wc3[i * 4 + o], s);
        h[o] = tanh_fast(s);
    }

    // q_tilde = (x @ rot) * 0.5*log2e ;  k = x @ ent
    float q[4], k[4];
    #pragma unroll
    for (int c = 0; c < 4; c++) {
        float sq = 0.f, sk = 0.f;
        #pragma unroll
        for (int i = 0; i < 4; i++) {
            sq = fmaf(h[i], rot[i * 4 + c], sq);
            sk = fmaf(h[i], ent[i * 4 + c], sk);
        }
        q[c] = sq * (0.5f * LOG2E);
        k[c] = sk;
    }

    gQ4[r] = make_float4(q[0], q[1], q[2], q[3]);

    // analytic bound: |x_i| <= 1 (tanh) => |k_c| <= sum_i |ent[i][c]|
    float A2 = 0.f;
    #pragma unroll
    for (int c = 0; c < 4; c++) {
        float ac = 0.f;
        #pragma unroll
        for (int i = 0; i < 4; i++) ac += fabsf(ent[i * 4 + c]);
        A2 = fmaf(ac, ac, A2);
    }
    float qn = sqrtf(q[0]*q[0] + q[1]*q[1] + q[2]*q[2] + q[3]*q[3]);
    gM[r] = -(qn * sqrtf(A2));

    ulonglong2 kxy, kzw;
    kxy.x = pack2(k[0], k[0]);
    kxy.y = pack2(k[1], k[1]);
    kzw.x = pack2(k[2], k[2]);
    kzw.y = pack2(k[3], k[3]);
    gKDxy[r] = kxy;
    gKDzw[r] = kzw;

    float cc = fmaf(h[0], conv_w[0], fmaf(h[1], conv_w[1],
               fmaf(h[2], conv_w[2], h[3] * conv_w[3])));
    gCCd[r] = pack2(cc, cc);
}

// ---------- Kernel B: streaming attention, f32x2-packed, 2 rows/pair, 4 pairs ----------
// exp2 args <= 0 via per-row Cauchy-Schwarz bound; slice partials (sum, y)
// combine by plain addition (row-constant offset cancels exactly in y/sum).
__global__ void __launch_bounds__(128) k_attn() {
    int t     = blockIdx.x * 128 + threadIdx.x;   // 0..RSTRIDE-1
    int slice = blockIdx.y;

    u64 qx[NPAIR], qy[NPAIR], qz[NPAIR], qw[NPAIR];
    u64 nm[NPAIR], sum[NPAIR], yy[NPAIR];

    #pragma unroll
    for (int p = 0; p < NPAIR; p++) {
        int r0 = t + (2 * p)     * RSTRIDE;
        int r1 = t + (2 * p + 1) * RSTRIDE;
        float4 qa = gQ4[r0];
        float4 qb = gQ4[r1];
        qx[p] = pack2(qa.x, qb.x);
        qy[p] = pack2(qa.y, qb.y);
        qz[p] = pack2(qa.z, qb.z);
        qw[p] = pack2(qa.w, qb.w);
        nm[p] = pack2(gM[r0], gM[r1]);
        sum[p] = pack2(0.f, 0.f);
        yy[p]  = pack2(0.f, 0.f);
    }

    const ulonglong2* __restrict__ kxyp = gKDxy;
    const ulonglong2* __restrict__ kzwp = gKDzw;
    const u64*        __restrict__ ccp  = gCCd;

    int j0 = slice * JPS;
    #pragma unroll 4
    for (int j = j0; j < j0 + JPS; j++) {
        ulonglong2 kxy = __ldg(kxyp + j);
        ulonglong2 kzw = __ldg(kzwp + j);
        u64        cc  = __ldg(ccp + j);
        #pragma unroll
        for (int p = 0; p < NPAIR; p++) {
            u64 s = ffma2(qx[p], kxy.x, nm[p]);
            s = ffma2(qy[p], kxy.y, s);
            s = ffma2(qz[p], kzw.x, s);
            s = ffma2(qw[p], kzw.y, s);
            float s0, s1;
            unpack2(s, s0, s1);
            u64 e = pack2(ex2f(s0), ex2f(s1));
            sum[p] = fadd2(sum[p], e);
            yy[p]  = ffma2(e, cc, yy[p]);
        }
    }

    #pragma unroll
    for (int p = 0; p < NPAIR; p++) {
        float s0, s1, y0, y1;
        unpack2(sum[p], s0, s1);
        unpack2(yy[p],  y0, y1);
        int r0 = t + (2 * p)     * RSTRIDE;
        int r1 = t + (2 * p + 1) * RSTRIDE;
        gP[r0 * NSLICE + slice] = make_float2(s0, y0);
        gP[r1 * NSLICE + slice] = make_float2(s1, y1);
    }
}

// ---------- Kernel C: reduce slices + conv-sigmoid + head-sigmoid ----------
__global__ void k_tail(const float* __restrict__ conv_b,
                       const float* __restrict__ head_w, const float* __restrict__ head_b,
                       float* __restrict__ out)
{
    int row = blockIdx.x * blockDim.x + threadIdx.x;
    if (row >= NB) return;

    const float4* p = reinterpret_cast<const float4*>(gP + row * NSLICE);
    float sum = 0.f, y = 0.f;
    #pragma unroll
    for (int i = 0; i < NSLICE / 2; i++) {
        float4 v = __ldg(p + i);      // {sum0, y0, sum1, y1}
        sum += v.x + v.z;
        y   += v.y + v.w;
    }
    float z = fmaf(y, 1.f / sum, conv_b[0]);
    float f = 1.f / (1.f + expf(-z));
    float logit = fmaf(f, head_w[0], head_b[0]);
    out[row] = 1.f / (1.f + expf(-logit));
}

extern "C" void kernel_launch(void* const* d_in, const int* in_sizes, int n_in,
                              void* d_out, int out_size)
{
    const float* inp  = (const float*)d_in[0];
    const float* Wfm  = (const float*)d_in[1];
    const float* bfm  = (const float*)d_in[2];
    const float* Wc1  = (const float*)d_in[3];
    const float* bc1  = (const float*)d_in[4];
    const float* Wp1  = (const float*)d_in[5];
    const float* bp1  = (const float*)d_in[6];
    const float* Wc2  = (const float*)d_in[7];
    const float* bc2  = (const float*)d_in[8];
    const float* Wp2  = (const float*)d_in[9];
    const float* bp2  = (const float*)d_in[10];
    const float* Wc3  = (const float*)d_in[11];
    const float* bc3  = (const float*)d_in[12];
    const float* rot  = (const float*)d_in[13];
    const float* ent  = (const float*)d_in[14];
    const float* cw   = (const float*)d_in[15];
    const float* cb   = (const float*)d_in[16];
    const float* hw   = (const float*)d_in[17];
    const float* hb   = (const float*)d_in[18];
    float* out = (float*)d_out;

    k_prep<<<NB / 128, 128>>>(inp, Wfm, bfm, Wc1, bc1, Wp1, bp1,
                              Wc2, bc2, Wp2, bp2, Wc3, bc3, rot, ent, cw);
    dim3 gridB(RSTRIDE / 128, NSLICE);
    k_attn<<<gridB, 128>>>();
    k_tail<<<NB / 128, 128>>>(cb, hw, hb, out);
}

// round 4
// speedup vs baseline: 2.6718x; 1.0654x over previous
#include <cuda_runtime.h>
#include <math.h>

#define NB 8192
#define NSLICE 37              // 4 x-blocks * 37 slices = 148 blocks = 1 block/SM
#define RPT 8                  // rows per thread in attention
#define RSTRIDE (NB / RPT)     // 1024
#define NPAIR (RPT / 2)        // 4 packed row-pairs
#define LOG2E 1.4426950408889634f

typedef unsigned long long u64;

// ---- scratch (device globals; no allocation allowed) ----
__device__ float4      gQ4[NB];        // q * (0.5*log2e) per row
__device__ float       gM[NB];         // -(|q_tilde| * kbound) per row
__device__ ulonglong2  gKDxy[NB];      // {pack(kx,kx), pack(ky,ky)}
__device__ ulonglong2  gKDzw[NB];      // {pack(kz,kz), pack(kw,kw)}
__device__ u64         gCCd[NB];       // pack(c,c), c = x . conv_w
__device__ float2      gP[NB * NSLICE];// {sum, y} partials, slice-contiguous per row

__device__ __forceinline__ float ex2f(float x) {
    float y;
    asm("ex2.approx.ftz.f32 %0, %1;" : "=f"(y) : "f"(x));
    return y;
}
__device__ __forceinline__ u64 ffma2(u64 a, u64 b, u64 c) {
    u64 d;
    asm("fma.rn.f32x2 %0, %1, %2, %3;" : "=l"(d) : "l"(a), "l"(b), "l"(c));
    return d;
}
__device__ __forceinline__ u64 fadd2(u64 a, u64 b) {
    u64 d;
    asm("add.rn.f32x2 %0, %1, %2;" : "=l"(d) : "l"(a), "l"(b));
    return d;
}
__device__ __forceinline__ u64 pack2(float lo, float hi) {
    u64 d;
    asm("mov.b64 %0, {%1, %2};" : "=l"(d) : "f"(lo), "f"(hi));
    return d;
}
__device__ __forceinline__ void unpack2(u64 v, float& lo, float& hi) {
    asm("mov.b64 {%0, %1}, %2;" : "=f"(lo), "=f"(hi) : "l"(v));
}
// fast tanh via ex2 + approximate division: err ~1e-6, MUFU-pipe only
__device__ __forceinline__ float tanh_fast(float x) {
    float e = ex2f(x * (2.0f * LOG2E));
    return 1.0f - __fdividef(2.0f, e + 1.0f);
}

// ---- smem weight layout (float offsets), all rows float4-aligned ----
#define O_WFM   0      // 8x16
#define O_BFM   128
#define O_WC1   144    // 16x16
#define O_BC1   400
#define O_WP1   416    // 16x12
#define O_BP1   608
#define O_WC2   620    // 12x8
#define O_BC2   716
#define O_WP2   724    // 8x4
#define O_BP2   756
#define O_WC3   760    // 4x4
#define O_BC3   776
#define O_ROT   780    // 4x4
#define O_ENT   796    // 4x4
#define O_CW    812    // 4
#define SM_FLOATS 816

template<int NI, int NO>
__device__ __forceinline__ void layer(const float* __restrict__ sm, int woff, int boff,
                                      const float* __restrict__ xin, float* __restrict__ xout)
{
    float acc[NO];
    #pragma unroll
    for (int o = 0; o < NO; o++) acc[o] = sm[boff + o];
    #pragma unroll
    for (int i = 0; i < NI; i++) {
        float xi = xin[i];
        #pragma unroll
        for (int g = 0; g < NO / 4; g++) {
            float4 w = *reinterpret_cast<const float4*>(sm + woff + i * NO + 4 * g);
            acc[4*g+0] = fmaf(xi, w.x, acc[4*g+0]);
            acc[4*g+1] = fmaf(xi, w.y, acc[4*g+1]);
            acc[4*g+2] = fmaf(xi, w.z, acc[4*g+2]);
            acc[4*g+3] = fmaf(xi, w.w, acc[4*g+3]);
        }
    }
    #pragma unroll
    for (int o = 0; o < NO; o++) xout[o] = tanh_fast(acc[o]);
}

__device__ __forceinline__ void stage(float* dst, const float* src, int n, int tid, int nthr) {
    for (int i = tid; i < n; i += nthr) dst[i] = src[i];
}

// ---------- Kernel A: MLP chain + q,k projection + conv scalar + row bound ----------
__global__ void __launch_bounds__(64) k_prep(
                       const float* __restrict__ inp,
                       const float* __restrict__ Wfm, const float* __restrict__ bfm,
                       const float* __restrict__ Wc1, const float* __restrict__ bc1,
                       const float* __restrict__ Wp1, const float* __restrict__ bp1,
                       const float* __restrict__ Wc2, const float* __restrict__ bc2,
                       const float* __restrict__ Wp2, const float* __restrict__ bp2,
                       const float* __restrict__ Wc3, const float* __restrict__ bc3,
                       const float* __restrict__ rot, const float* __restrict__ ent,
                       const float* __restrict__ conv_w)
{
    __shared__ float sm[SM_FLOATS];
    int tid = threadIdx.x;
    stage(sm + O_WFM, Wfm, 128, tid, 64);
    stage(sm + O_BFM, bfm, 16,  tid, 64);
    stage(sm + O_WC1, Wc1, 256, tid, 64);
    stage(sm + O_BC1, bc1, 16,  tid, 64);
    stage(sm + O_WP1, Wp1, 192, tid, 64);
    stage(sm + O_BP1, bp1, 12,  tid, 64);
    stage(sm + O_WC2, Wc2, 96,  tid, 64);
    stage(sm + O_BC2, bc2, 8,   tid, 64);
    stage(sm + O_WP2, Wp2, 32,  tid, 64);
    stage(sm + O_BP2, bp2, 4,   tid, 64);
    stage(sm + O_WC3, Wc3, 16,  tid, 64);
    stage(sm + O_BC3, bc3, 4,   tid, 64);
    stage(sm + O_ROT, rot, 16,  tid, 64);
    stage(sm + O_ENT, ent, 16,  tid, 64);
    stage(sm + O_CW,  conv_w, 4, tid, 64);
    __syncthreads();

    int r = blockIdx.x * 64 + tid;

    float in0[16], h[16];
    {
        const float4* ip = reinterpret_cast<const float4*>(inp + r * 8);
        float4 v0 = __ldg(ip), v1 = __ldg(ip + 1);
        in0[0]=v0.x; in0[1]=v0.y; in0[2]=v0.z; in0[3]=v0.w;
        in0[4]=v1.x; in0[5]=v1.y; in0[6]=v1.z; in0[7]=v1.w;
    }

    layer<8, 16>(sm, O_WFM, O_BFM, in0, h);
    layer<16,16>(sm, O_WC1, O_BC1, h, in0);
    layer<16,12>(sm, O_WP1, O_BP1, in0, h);
    layer<12, 8>(sm, O_WC2, O_BC2, h, in0);
    layer<8,  4>(sm, O_WP2, O_BP2, in0, h);
    layer<4,  4>(sm, O_WC3, O_BC3, h, in0);   // final x in in0[0..3]

    // q_tilde = (x @ rot) * 0.5*log2e ;  k = x @ ent
    float q[4], k[4];
    #pragma unroll
    for (int c = 0; c < 4; c++) {
        float sq = 0.f, sk = 0.f;
        #pragma unroll
        for (int i = 0; i < 4; i++) {
            sq = fmaf(in0[i], sm[O_ROT + i * 4 + c], sq);
            sk = fmaf(in0[i], sm[O_ENT + i * 4 + c], sk);
        }
        q[c] = sq * (0.5f * LOG2E);
        k[c] = sk;
    }

    gQ4[r] = make_float4(q[0], q[1], q[2], q[3]);

    // analytic bound: |x_i| <= 1 (tanh) => |k_c| <= sum_i |ent[i][c]|
    float A2 = 0.f;
    #pragma unroll
    for (int c = 0; c < 4; c++) {
        float ac = 0.f;
        #pragma unroll
        for (int i = 0; i < 4; i++) ac += fabsf(sm[O_ENT + i * 4 + c]);
        A2 = fmaf(ac, ac, A2);
    }
    float qn = sqrtf(q[0]*q[0] + q[1]*q[1] + q[2]*q[2] + q[3]*q[3]);
    gM[r] = -(qn * sqrtf(A2));

    ulonglong2 kxy, kzw;
    kxy.x = pack2(k[0], k[0]);
    kxy.y = pack2(k[1], k[1]);
    kzw.x = pack2(k[2], k[2]);
    kzw.y = pack2(k[3], k[3]);
    gKDxy[r] = kxy;
    gKDzw[r] = kzw;

    float cc = fmaf(in0[0], sm[O_CW+0], fmaf(in0[1], sm[O_CW+1],
               fmaf(in0[2], sm[O_CW+2], in0[3] * sm[O_CW+3])));
    gCCd[r] = pack2(cc, cc);
}

// ---------- Kernel B: streaming attention, f32x2-packed, single wave of 148 blocks ----------
// exp2 args <= 0 via per-row Cauchy-Schwarz bound; slice partials (sum, y)
// combine by plain addition (row-constant offset cancels exactly in y/sum).
__global__ void __launch_bounds__(256) k_attn() {
    int t     = blockIdx.x * 256 + threadIdx.x;   // 0..RSTRIDE-1
    int slice = blockIdx.y;

    u64 qx[NPAIR], qy[NPAIR], qz[NPAIR], qw[NPAIR];
    u64 nm[NPAIR], sum[NPAIR], yy[NPAIR];

    #pragma unroll
    for (int p = 0; p < NPAIR; p++) {
        int r0 = t + (2 * p)     * RSTRIDE;
        int r1 = t + (2 * p + 1) * RSTRIDE;
        float4 qa = gQ4[r0];
        float4 qb = gQ4[r1];
        qx[p] = pack2(qa.x, qb.x);
        qy[p] = pack2(qa.y, qb.y);
        qz[p] = pack2(qa.z, qb.z);
        qw[p] = pack2(qa.w, qb.w);
        nm[p] = pack2(gM[r0], gM[r1]);
        sum[p] = pack2(0.f, 0.f);
        yy[p]  = pack2(0.f, 0.f);
    }

    const ulonglong2* __restrict__ kxyp = gKDxy;
    const ulonglong2* __restrict__ kzwp = gKDzw;
    const u64*        __restrict__ ccp  = gCCd;

    int j0 = (slice * NB) / NSLICE;
    int j1 = ((slice + 1) * NB) / NSLICE;
    #pragma unroll 4
    for (int j = j0; j < j1; j++) {
        ulonglong2 kxy = __ldg(kxyp + j);
        ulonglong2 kzw = __ldg(kzwp + j);
        u64        cc  = __ldg(ccp + j);
        #pragma unroll
        for (int p = 0; p < NPAIR; p++) {
            u64 s = ffma2(qx[p], kxy.x, nm[p]);
            s = ffma2(qy[p], kxy.y, s);
            s = ffma2(qz[p], kzw.x, s);
            s = ffma2(qw[p], kzw.y, s);
            float s0, s1;
            unpack2(s, s0, s1);
            u64 e = pack2(ex2f(s0), ex2f(s1));
            sum[p] = fadd2(sum[p], e);
            yy[p]  = ffma2(e, cc, yy[p]);
        }
    }

    #pragma unroll
    for (int p = 0; p < NPAIR; p++) {
        float s0, s1, y0, y1;
        unpack2(sum[p], s0, s1);
        unpack2(yy[p],  y0, y1);
        int r0 = t + (2 * p)     * RSTRIDE;
        int r1 = t + (2 * p + 1) * RSTRIDE;
        gP[r0 * NSLICE + slice] = make_float2(s0, y0);
        gP[r1 * NSLICE + slice] = make_float2(s1, y1);
    }
}

// ---------- Kernel C: reduce slices + conv-sigmoid + head-sigmoid ----------
__global__ void __launch_bounds__(64) k_tail(
                       const float* __restrict__ conv_b,
                       const float* __restrict__ head_w, const float* __restrict__ head_b,
                       float* __restrict__ out)
{
    int row = blockIdx.x * 64 + threadIdx.x;

    const float2* __restrict__ p = gP + row * NSLICE;
    float sum = 0.f, y = 0.f;
    #pragma unroll
    for (int s = 0; s < NSLICE; s++) {
        float2 v = __ldg(p + s);
        sum += v.x;
        y   += v.y;
    }
    float z = fmaf(y, 1.f / sum, conv_b[0]);
    float f = 1.f / (1.f + expf(-z));
    float logit = fmaf(f, head_w[0], head_b[0]);
    out[row] = 1.f / (1.f + expf(-logit));
}

extern "C" void kernel_launch(void* const* d_in, const int* in_sizes, int n_in,
                              void* d_out, int out_size)
{
    const float* inp  = (const float*)d_in[0];
    const float* Wfm  = (const float*)d_in[1];
    const float* bfm  = (const float*)d_in[2];
    const float* Wc1  = (const float*)d_in[3];
    const float* bc1  = (const float*)d_in[4];
    const float* Wp1  = (const float*)d_in[5];
    const float* bp1  = (const float*)d_in[6];
    const float* Wc2  = (const float*)d_in[7];
    const float* bc2  = (const float*)d_in[8];
    const float* Wp2  = (const float*)d_in[9];
    const float* bp2  = (const float*)d_in[10];
    const float* Wc3  = (const float*)d_in[11];
    const float* bc3  = (const float*)d_in[12];
    const float* rot  = (const float*)d_in[13];
    const float* ent  = (const float*)d_in[14];
    const float* cw   = (const float*)d_in[15];
    const float* cb   = (const float*)d_in[16];
    const float* hw   = (const float*)d_in[17];
    const float* hb   = (const float*)d_in[18];
    float* out = (float*)d_out;

    k_prep<<<NB / 64, 64>>>(inp, Wfm, bfm, Wc1, bc1, Wp1, bp1,
                            Wc2, bc2, Wp2, bp2, Wc3, bc3, rot, ent, cw);
    dim3 gridB(RSTRIDE / 256, NSLICE);   // 4 x 37 = 148 blocks
    k_attn<<<gridB, 256>>>();
    k_tail<<<NB / 64, 64>>>(cb, hw, hb, out);
}

// round 5
// speedup vs baseline: 5.1120x; 1.9133x over previous
#include <cuda_runtime.h>
#include <math.h>

#define NB 8192
#define NSLICE 37              // 4 x-blocks * 37 slices = 148 blocks = 1 block/SM
#define PSTRIDE 38             // padded partial stride (19 float4 per row)
#define RPT 4                  // rows per thread in attention
#define RSTRIDE (NB / RPT)     // 2048
#define NPAIR (RPT / 2)        // 2 packed row-pairs
#define JMAX 222               // max j per slice (ceil(8192/37))
#define LOG2E 1.4426950408889634f

typedef unsigned long long u64;

// ---- scratch (device globals; no allocation allowed) ----
__device__ float4      gQ4[NB];        // q * (0.5*log2e) per row
__device__ float       gM[NB];         // -(|q_tilde| * kbound) per row
__device__ ulonglong2  gKDxy[NB];      // {pack(kx,kx), pack(ky,ky)}
__device__ ulonglong2  gKDzw[NB];      // {pack(kz,kz), pack(kw,kw)}
__device__ u64         gCCd[NB];       // pack(c,c), c = x . conv_w
__device__ float4      gP[NB * PSTRIDE / 2];  // {sum,y} float2 pairs, padded; pad stays 0

__device__ __forceinline__ float ex2f(float x) {
    float y;
    asm("ex2.approx.ftz.f32 %0, %1;" : "=f"(y) : "f"(x));
    return y;
}
__device__ __forceinline__ u64 ffma2(u64 a, u64 b, u64 c) {
    u64 d;
    asm("fma.rn.f32x2 %0, %1, %2, %3;" : "=l"(d) : "l"(a), "l"(b), "l"(c));
    return d;
}
__device__ __forceinline__ u64 fadd2(u64 a, u64 b) {
    u64 d;
    asm("add.rn.f32x2 %0, %1, %2;" : "=l"(d) : "l"(a), "l"(b));
    return d;
}
__device__ __forceinline__ u64 pack2(float lo, float hi) {
    u64 d;
    asm("mov.b64 %0, {%1, %2};" : "=l"(d) : "f"(lo), "f"(hi));
    return d;
}
__device__ __forceinline__ void unpack2(u64 v, float& lo, float& hi) {
    asm("mov.b64 {%0, %1}, %2;" : "=f"(lo), "=f"(hi) : "l"(v));
}
// fast tanh via ex2 + approximate reciprocal: err ~1e-6
__device__ __forceinline__ float tanh_fast(float x) {
    float e = ex2f(x * (2.0f * LOG2E));
    return 1.0f - __fdividef(2.0f, e + 1.0f);
}

// ---- smem weight layout (float offsets) ----
#define O_WFM   0      // 8x16
#define O_BFM   128
#define O_WC1   144    // 16x16
#define O_BC1   400
#define O_WP1   416    // 16x12
#define O_BP1   608
#define O_WC2   620    // 12x8
#define O_BC2   716
#define O_WP2   724    // 8x4
#define O_BP2   756
#define O_WC3   760    // 4x4
#define O_BC3   776
#define O_ROT   780    // 4x4
#define O_ENT   796    // 4x4
#define O_CW    812    // 4
#define SM_FLOATS 816

// 4-lane cooperative layer: lane q computes outputs [q*NO/4, (q+1)*NO/4),
// then the full activation vector is re-assembled via width-4 shuffles.
template<int NI, int NO>
__device__ __forceinline__ void layer4(const float* __restrict__ smw, int woff, int boff,
                                       int q, const float* __restrict__ xin,
                                       float* __restrict__ xout_full)
{
    constexpr int NOq = NO / 4;
    float acc[NOq];
    #pragma unroll
    for (int oo = 0; oo < NOq; oo++) acc[oo] = smw[boff + q * NOq + oo];
    #pragma unroll
    for (int i = 0; i < NI; i++) {
        float xi = xin[i];
        #pragma unroll
        for (int oo = 0; oo < NOq; oo++)
            acc[oo] = fmaf(xi, smw[woff + i * NO + q * NOq + oo], acc[oo]);
    }
    float loc[NOq];
    #pragma unroll
    for (int oo = 0; oo < NOq; oo++) loc[oo] = tanh_fast(acc[oo]);
    #pragma unroll
    for (int i = 0; i < NO; i++)
        xout_full[i] = __shfl_sync(0xffffffffu, loc[i % NOq], i / NOq, 4);
}

__device__ __forceinline__ void stage(float* dst, const float* src, int n, int tid, int nthr) {
    for (int i = tid; i < n; i += nthr) dst[i] = src[i];
}

// ---------- Kernel A: MLP chain, 4 lanes per row ----------
__global__ void __launch_bounds__(256) k_prep(
                       const float* __restrict__ inp,
                       const float* __restrict__ Wfm, const float* __restrict__ bfm,
                       const float* __restrict__ Wc1, const float* __restrict__ bc1,
                       const float* __restrict__ Wp1, const float* __restrict__ bp1,
                       const float* __restrict__ Wc2, const float* __restrict__ bc2,
                       const float* __restrict__ Wp2, const float* __restrict__ bp2,
                       const float* __restrict__ Wc3, const float* __restrict__ bc3,
                       const float* __restrict__ rot, const float* __restrict__ ent,
                       const float* __restrict__ conv_w)
{
    __shared__ float sm[SM_FLOATS];
    int tid = threadIdx.x;
    stage(sm + O_WFM, Wfm, 128, tid, 256);
    stage(sm + O_BFM, bfm, 16,  tid, 256);
    stage(sm + O_WC1, Wc1, 256, tid, 256);
    stage(sm + O_BC1, bc1, 16,  tid, 256);
    stage(sm + O_WP1, Wp1, 192, tid, 256);
    stage(sm + O_BP1, bp1, 12,  tid, 256);
    stage(sm + O_WC2, Wc2, 96,  tid, 256);
    stage(sm + O_BC2, bc2, 8,   tid, 256);
    stage(sm + O_WP2, Wp2, 32,  tid, 256);
    stage(sm + O_BP2, bp2, 4,   tid, 256);
    stage(sm + O_WC3, Wc3, 16,  tid, 256);
    stage(sm + O_BC3, bc3, 4,   tid, 256);
    stage(sm + O_ROT, rot, 16,  tid, 256);
    stage(sm + O_ENT, ent, 16,  tid, 256);
    stage(sm + O_CW,  conv_w, 4, tid, 256);
    __syncthreads();

    int r = blockIdx.x * 64 + (tid >> 2);   // row
    int q = tid & 3;                        // lane within row

    float x0[16], x1[16];
    {
        const float4* ip = reinterpret_cast<const float4*>(inp + r * 8);
        float4 v0 = __ldg(ip), v1 = __ldg(ip + 1);
        x0[0]=v0.x; x0[1]=v0.y; x0[2]=v0.z; x0[3]=v0.w;
        x0[4]=v1.x; x0[5]=v1.y; x0[6]=v1.z; x0[7]=v1.w;
    }

    layer4<8, 16>(sm, O_WFM, O_BFM, q, x0, x1);
    layer4<16,16>(sm, O_WC1, O_BC1, q, x1, x0);
    layer4<16,12>(sm, O_WP1, O_BP1, q, x0, x1);
    layer4<12, 8>(sm, O_WC2, O_BC2, q, x1, x0);
    layer4<8,  4>(sm, O_WP2, O_BP2, q, x0, x1);
    layer4<4,  4>(sm, O_WC3, O_BC3, q, x1, x0);   // final x in x0[0..3]

    // q_tilde = (x @ rot) * 0.5*log2e ;  k = x @ ent  (all 4 lanes redundant)
    float qv[4], kv[4];
    #pragma unroll
    for (int c = 0; c < 4; c++) {
        float sq = 0.f, sk = 0.f;
        #pragma unroll
        for (int i = 0; i < 4; i++) {
            sq = fmaf(x0[i], sm[O_ROT + i * 4 + c], sq);
            sk = fmaf(x0[i], sm[O_ENT + i * 4 + c], sk);
        }
        qv[c] = sq * (0.5f * LOG2E);
        kv[c] = sk;
    }

    // analytic bound: |x_i| <= 1 (tanh) => |k_c| <= sum_i |ent[i][c]|
    float A2 = 0.f;
    #pragma unroll
    for (int c = 0; c < 4; c++) {
        float ac = 0.f;
        #pragma unroll
        for (int i = 0; i < 4; i++) ac += fabsf(sm[O_ENT + i * 4 + c]);
        A2 = fmaf(ac, ac, A2);
    }

    if (q == 0) {
        gQ4[r] = make_float4(qv[0], qv[1], qv[2], qv[3]);
        float qn = sqrtf(qv[0]*qv[0] + qv[1]*qv[1] + qv[2]*qv[2] + qv[3]*qv[3]);
        gM[r] = -(qn * sqrtf(A2));
        ulonglong2 kxy, kzw;
        kxy.x = pack2(kv[0], kv[0]);
        kxy.y = pack2(kv[1], kv[1]);
        kzw.x = pack2(kv[2], kv[2]);
        kzw.y = pack2(kv[3], kv[3]);
        gKDxy[r] = kxy;
        gKDzw[r] = kzw;
        float cc = fmaf(x0[0], sm[O_CW+0], fmaf(x0[1], sm[O_CW+1],
                   fmaf(x0[2], sm[O_CW+2], x0[3] * sm[O_CW+3])));
        gCCd[r] = pack2(cc, cc);
    }
}

// ---------- Kernel B: streaming attention, f32x2-packed, smem-staged K ----------
__global__ void __launch_bounds__(512) k_attn() {
    __shared__ ulonglong2 smKxy[JMAX];
    __shared__ ulonglong2 smKzw[JMAX];
    __shared__ u64        smCc[JMAX];

    int tid   = threadIdx.x;
    int t     = blockIdx.x * 512 + tid;   // 0..RSTRIDE-1
    int slice = blockIdx.y;

    int j0  = (slice * NB) / NSLICE;
    int cnt = ((slice + 1) * NB) / NSLICE - j0;

    if (tid < cnt) {
        smKxy[tid] = gKDxy[j0 + tid];
        smKzw[tid] = gKDzw[j0 + tid];
        smCc[tid]  = gCCd[j0 + tid];
    }

    u64 qx[NPAIR], qy[NPAIR], qz[NPAIR], qw[NPAIR];
    u64 nm[NPAIR], sum[NPAIR], yy[NPAIR];

    #pragma unroll
    for (int p = 0; p < NPAIR; p++) {
        int r0 = t + (2 * p)     * RSTRIDE;
        int r1 = t + (2 * p + 1) * RSTRIDE;
        float4 qa = gQ4[r0];
        float4 qb = gQ4[r1];
        qx[p] = pack2(qa.x, qb.x);
        qy[p] = pack2(qa.y, qb.y);
        qz[p] = pack2(qa.z, qb.z);
        qw[p] = pack2(qa.w, qb.w);
        nm[p] = pack2(gM[r0], gM[r1]);
        sum[p] = pack2(0.f, 0.f);
        yy[p]  = pack2(0.f, 0.f);
    }

    __syncthreads();

    #pragma unroll 4
    for (int j = 0; j < cnt; j++) {
        ulonglong2 kxy = smKxy[j];
        ulonglong2 kzw = smKzw[j];
        u64        cc  = smCc[j];
        #pragma unroll
        for (int p = 0; p < NPAIR; p++) {
            u64 s = ffma2(qx[p], kxy.x, nm[p]);
            s = ffma2(qy[p], kxy.y, s);
            s = ffma2(qz[p], kzw.x, s);
            s = ffma2(qw[p], kzw.y, s);
            float s0, s1;
            unpack2(s, s0, s1);
            u64 e = pack2(ex2f(s0), ex2f(s1));
            sum[p] = fadd2(sum[p], e);
            yy[p]  = ffma2(e, cc, yy[p]);
        }
    }

    float2* __restrict__ gp2 = reinterpret_cast<float2*>(gP);
    #pragma unroll
    for (int p = 0; p < NPAIR; p++) {
        float s0, s1, y0, y1;
        unpack2(sum[p], s0, s1);
        unpack2(yy[p],  y0, y1);
        int r0 = t + (2 * p)     * RSTRIDE;
        int r1 = t + (2 * p + 1) * RSTRIDE;
        gp2[r0 * PSTRIDE + slice] = make_float2(s0, y0);
        gp2[r1 * PSTRIDE + slice] = make_float2(s1, y1);
    }
}

// ---------- Kernel C: reduce slices + conv-sigmoid + head-sigmoid ----------
__global__ void __launch_bounds__(128) k_tail(
                       const float* __restrict__ conv_b,
                       const float* __restrict__ head_w, const float* __restrict__ head_b,
                       float* __restrict__ out)
{
    int row = blockIdx.x * 128 + threadIdx.x;

    // 19 aligned float4 per row; pad slot (slice 37) is never written -> 0
    const float4* __restrict__ p = gP + row * (PSTRIDE / 2);
    float sum = 0.f, y = 0.f;
    #pragma unroll
    for (int i = 0; i < PSTRIDE / 2; i++) {
        float4 v = __ldg(p + i);      // {sum0, y0, sum1, y1}
        sum += v.x + v.z;
        y   += v.y + v.w;
    }
    float z = fmaf(y, 1.f / sum, conv_b[0]);
    float f = 1.f / (1.f + expf(-z));
    float logit = fmaf(f, head_w[0], head_b[0]);
    out[row] = 1.f / (1.f + expf(-logit));
}

extern "C" void kernel_launch(void* const* d_in, const int* in_sizes, int n_in,
                              void* d_out, int out_size)
{
    const float* inp  = (const float*)d_in[0];
    const float* Wfm  = (const float*)d_in[1];
    const float* bfm  = (const float*)d_in[2];
    const float* Wc1  = (const float*)d_in[3];
    const float* bc1  = (const float*)d_in[4];
    const float* Wp1  = (const float*)d_in[5];
    const float* bp1  = (const float*)d_in[6];
    const float* Wc2  = (const float*)d_in[7];
    const float* bc2  = (const float*)d_in[8];
    const float* Wp2  = (const float*)d_in[9];
    const float* bp2  = (const float*)d_in[10];
    const float* Wc3  = (const float*)d_in[11];
    const float* bc3  = (const float*)d_in[12];
    const float* rot  = (const float*)d_in[13];
    const float* ent  = (const float*)d_in[14];
    const float* cw   = (const float*)d_in[15];
    const float* cb   = (const float*)d_in[16];
    const float* hw   = (const float*)d_in[17];
    const float* hb   = (const float*)d_in[18];
    float* out = (float*)d_out;

    k_prep<<<NB / 64, 256>>>(inp, Wfm, bfm, Wc1, bc1, Wp1, bp1,
                             Wc2, bc2, Wp2, bp2, Wc3, bc3, rot, ent, cw);
    dim3 gridB(RSTRIDE / 512, NSLICE);   // 4 x 37 = 148 blocks, 16 warps each
    k_attn<<<gridB, 512>>>();
    k_tail<<<NB / 128, 128>>>(cb, hw, hb, out);
}

// round 7
// speedup vs baseline: 5.2444x; 1.0259x over previous
#include <cuda_runtime.h>
#include <math.h>

#define NB 8192
#define NSLICE 37              // 4 x-blocks * 37 slices = 148 blocks = 1 block/SM
#define PSTRIDE 38             // padded partial stride (19 float4 per row); pad slot stays 0
#define RPT 4                  // rows per thread in attention
#define RSTRIDE (NB / RPT)     // 2048
#define NPAIR (RPT / 2)        // 2 packed row-pairs
#define JMAX 222               // max j per slice (ceil(8192/37))
#define LOG2E 1.4426950408889634f

typedef unsigned long long u64;

// ---- scratch (device globals; no allocation allowed) ----
__device__ float4      gQ4[NB];        // q * (0.5*log2e) per row
__device__ float       gM[NB];         // -(|q_tilde| * kbound) per row
__device__ ulonglong2  gKDxy[NB];      // {pack(kx,kx), pack(ky,ky)}
__device__ ulonglong2  gKDzw[NB];      // {pack(kz,kz), pack(kw,kw)}
__device__ u64         gCCd[NB];       // pack(c,c), c = x . conv_w
__device__ float4      gP[NB * PSTRIDE / 2];  // {sum,y} float2 pairs, padded; pad stays 0

__device__ __forceinline__ float ex2f(float x) {
    float y;
    asm("ex2.approx.ftz.f32 %0, %1;" : "=f"(y) : "f"(x));
    return y;
}
__device__ __forceinline__ u64 ffma2(u64 a, u64 b, u64 c) {
    u64 d;
    asm("fma.rn.f32x2 %0, %1, %2, %3;" : "=l"(d) : "l"(a), "l"(b), "l"(c));
    return d;
}
__device__ __forceinline__ u64 fadd2(u64 a, u64 b) {
    u64 d;
    asm("add.rn.f32x2 %0, %1, %2;" : "=l"(d) : "l"(a), "l"(b));
    return d;
}
__device__ __forceinline__ u64 pack2(float lo, float hi) {
    u64 d;
    asm("mov.b64 %0, {%1, %2};" : "=l"(d) : "f"(lo), "f"(hi));
    return d;
}
__device__ __forceinline__ void unpack2(u64 v, float& lo, float& hi) {
    asm("mov.b64 {%0, %1}, %2;" : "=f"(lo), "=f"(hi) : "l"(v));
}
// fast tanh via ex2 + approximate reciprocal: err ~1e-6
__device__ __forceinline__ float tanh_fast(float x) {
    float e = ex2f(x * (2.0f * LOG2E));
    return 1.0f - __fdividef(2.0f, e + 1.0f);
}

// ---- smem weight layout (float offsets); all 16B-aligned where vectorized ----
#define O_WFM   0      // 8x16
#define O_BFM   128
#define O_WC1   144    // 16x16  (144*4=576B, 16B aligned)
#define O_BC1   400
#define O_WP1   416    // 16x12
#define O_BP1   608
#define O_WC2   620    // 12x8   (620*4=2480B, 8B aligned)
#define O_BC2   716
#define O_WP2   724    // 8x4
#define O_BP2   756
#define O_WC3   760    // 4x4
#define O_BC3   776
#define O_ROT   780
#define O_ENT   796
#define O_CW    812
#define SM_FLOATS 816

// 4-lane cooperative layer: lane q computes outputs [q*NO/4, (q+1)*NO/4),
// weights loaded vectorized (float4 for NO=16, float2 for NO=8), then the
// full activation vector is re-assembled via width-4 shuffles.
template<int NI, int NO>
__device__ __forceinline__ void layer4(const float* __restrict__ smw, int woff, int boff,
                                       int q, const float* __restrict__ xin,
                                       float* __restrict__ xout_full)
{
    constexpr int NOq = NO / 4;
    float acc[NOq];
    #pragma unroll
    for (int oo = 0; oo < NOq; oo++) acc[oo] = smw[boff + q * NOq + oo];
    #pragma unroll
    for (int i = 0; i < NI; i++) {
        float xi = xin[i];
        if constexpr (NOq == 4) {
            float4 w = *reinterpret_cast<const float4*>(smw + woff + i * NO + q * 4);
            acc[0] = fmaf(xi, w.x, acc[0]);
            acc[1] = fmaf(xi, w.y, acc[1]);
            acc[2] = fmaf(xi, w.z, acc[2]);
            acc[3] = fmaf(xi, w.w, acc[3]);
        } else if constexpr (NOq == 2) {
            float2 w = *reinterpret_cast<const float2*>(smw + woff + i * NO + q * 2);
            acc[0] = fmaf(xi, w.x, acc[0]);
            acc[1] = fmaf(xi, w.y, acc[1]);
        } else {
            #pragma unroll
            for (int oo = 0; oo < NOq; oo++)
                acc[oo] = fmaf(xi, smw[woff + i * NO + q * NOq + oo], acc[oo]);
        }
    }
    float loc[NOq];
    #pragma unroll
    for (int oo = 0; oo < NOq; oo++) loc[oo] = tanh_fast(acc[oo]);
    #pragma unroll
    for (int i = 0; i < NO; i++)
        xout_full[i] = __shfl_sync(0xffffffffu, loc[i % NOq], i / NOq, 4);
}

__device__ __forceinline__ void stage(float* dst, const float* src, int n, int tid, int nthr) {
    for (int i = tid; i < n; i += nthr) dst[i] = src[i];
}

// ---------- Kernel A: MLP chain, 4 lanes per row ----------
__global__ void __launch_bounds__(256) k_prep(
                       const float* __restrict__ inp,
                       const float* __restrict__ Wfm, const float* __restrict__ bfm,
                       const float* __restrict__ Wc1, const float* __restrict__ bc1,
                       const float* __restrict__ Wp1, const float* __restrict__ bp1,
                       const float* __restrict__ Wc2, const float* __restrict__ bc2,
                       const float* __restrict__ Wp2, const float* __restrict__ bp2,
                       const float* __restrict__ Wc3, const float* __restrict__ bc3,
                       const float* __restrict__ rot, const float* __restrict__ ent,
                       const float* __restrict__ conv_w)
{
    __shared__ __align__(16) float sm[SM_FLOATS];
    int tid = threadIdx.x;
    stage(sm + O_WFM, Wfm, 128, tid, 256);
    stage(sm + O_BFM, bfm, 16,  tid, 256);
    stage(sm + O_WC1, Wc1, 256, tid, 256);
    stage(sm + O_BC1, bc1, 16,  tid, 256);
    stage(sm + O_WP1, Wp1, 192, tid, 256);
    stage(sm + O_BP1, bp1, 12,  tid, 256);
    stage(sm + O_WC2, Wc2, 96,  tid, 256);
    stage(sm + O_BC2, bc2, 8,   tid, 256);
    stage(sm + O_WP2, Wp2, 32,  tid, 256);
    stage(sm + O_BP2, bp2, 4,   tid, 256);
    stage(sm + O_WC3, Wc3, 16,  tid, 256);
    stage(sm + O_BC3, bc3, 4,   tid, 256);
    stage(sm + O_ROT, rot, 16,  tid, 256);
    stage(sm + O_ENT, ent, 16,  tid, 256);
    stage(sm + O_CW,  conv_w, 4, tid, 256);
    __syncthreads();

    int r = blockIdx.x * 64 + (tid >> 2);   // row
    int q = tid & 3;                        // lane within row

    float x0[16], x1[16];
    {
        const float4* ip = reinterpret_cast<const float4*>(inp + r * 8);
        float4 v0 = __ldg(ip), v1 = __ldg(ip + 1);
        x0[0]=v0.x; x0[1]=v0.y; x0[2]=v0.z; x0[3]=v0.w;
        x0[4]=v1.x; x0[5]=v1.y; x0[6]=v1.z; x0[7]=v1.w;
    }

    layer4<8, 16>(sm, O_WFM, O_BFM, q, x0, x1);
    layer4<16,16>(sm, O_WC1, O_BC1, q, x1, x0);
    layer4<16,12>(sm, O_WP1, O_BP1, q, x0, x1);
    layer4<12, 8>(sm, O_WC2, O_BC2, q, x1, x0);
    layer4<8,  4>(sm, O_WP2, O_BP2, q, x0, x1);
    layer4<4,  4>(sm, O_WC3, O_BC3, q, x1, x0);   // final x in x0[0..3]

    if (q == 0) {
        float qv[4], kv[4];
        #pragma unroll
        for (int c = 0; c < 4; c++) {
            float sq = 0.f, sk = 0.f;
            #pragma unroll
            for (int i = 0; i < 4; i++) {
                sq = fmaf(x0[i], sm[O_ROT + i * 4 + c], sq);
                sk = fmaf(x0[i], sm[O_ENT + i * 4 + c], sk);
            }
            qv[c] = sq * (0.5f * LOG2E);
            kv[c] = sk;
        }

        // analytic bound: |x_i| <= 1 (tanh) => |k_c| <= sum_i |ent[i][c]|
        float A2 = 0.f;
        #pragma unroll
        for (int c = 0; c < 4; c++) {
            float ac = 0.f;
            #pragma unroll
            for (int i = 0; i < 4; i++) ac += fabsf(sm[O_ENT + i * 4 + c]);
            A2 = fmaf(ac, ac, A2);
        }

        gQ4[r] = make_float4(qv[0], qv[1], qv[2], qv[3]);
        float qn = sqrtf(qv[0]*qv[0] + qv[1]*qv[1] + qv[2]*qv[2] + qv[3]*qv[3]);
        gM[r] = -(qn * sqrtf(A2));
        ulonglong2 kxy, kzw;
        kxy.x = pack2(kv[0], kv[0]);
        kxy.y = pack2(kv[1], kv[1]);
        kzw.x = pack2(kv[2], kv[2]);
        kzw.y = pack2(kv[3], kv[3]);
        gKDxy[r] = kxy;
        gKDzw[r] = kzw;
        float cc = fmaf(x0[0], sm[O_CW+0], fmaf(x0[1], sm[O_CW+1],
                   fmaf(x0[2], sm[O_CW+2], x0[3] * sm[O_CW+3])));
        gCCd[r] = pack2(cc, cc);
    }
}

// ---------- Kernel B: streaming attention, f32x2-packed, smem-staged K ----------
__global__ void __launch_bounds__(512) k_attn() {
    __shared__ ulonglong2 smKxy[JMAX];
    __shared__ ulonglong2 smKzw[JMAX];
    __shared__ u64        smCc[JMAX];

    int tid   = threadIdx.x;
    int t     = blockIdx.x * 512 + tid;   // 0..RSTRIDE-1
    int slice = blockIdx.y;

    int j0  = (slice * NB) / NSLICE;
    int cnt = ((slice + 1) * NB) / NSLICE - j0;

    if (tid < cnt) {
        smKxy[tid] = gKDxy[j0 + tid];
        smKzw[tid] = gKDzw[j0 + tid];
        smCc[tid]  = gCCd[j0 + tid];
    }

    u64 qx[NPAIR], qy[NPAIR], qz[NPAIR], qw[NPAIR];
    u64 nm[NPAIR], sum[NPAIR], yy[NPAIR];

    #pragma unroll
    for (int p = 0; p < NPAIR; p++) {
        int r0 = t + (2 * p)     * RSTRIDE;
        int r1 = t + (2 * p + 1) * RSTRIDE;
        float4 qa = gQ4[r0];
        float4 qb = gQ4[r1];
        qx[p] = pack2(qa.x, qb.x);
        qy[p] = pack2(qa.y, qb.y);
        qz[p] = pack2(qa.z, qb.z);
        qw[p] = pack2(qa.w, qb.w);
        nm[p] = pack2(gM[r0], gM[r1]);
        sum[p] = pack2(0.f, 0.f);
        yy[p]  = pack2(0.f, 0.f);
    }

    __syncthreads();

    #pragma unroll 4
    for (int j = 0; j < cnt; j++) {
        ulonglong2 kxy = smKxy[j];
        ulonglong2 kzw = smKzw[j];
        u64        cc  = smCc[j];
        #pragma unroll
        for (int p = 0; p < NPAIR; p++) {
            u64 s = ffma2(qx[p], kxy.x, nm[p]);
            s = ffma2(qy[p], kxy.y, s);
            s = ffma2(qz[p], kzw.x, s);
            s = ffma2(qw[p], kzw.y, s);
            float s0, s1;
            unpack2(s, s0, s1);
            u64 e = pack2(ex2f(s0), ex2f(s1));
            sum[p] = fadd2(sum[p], e);
            yy[p]  = ffma2(e, cc, yy[p]);
        }
    }

    float2* __restrict__ gp2 = reinterpret_cast<float2*>(gP);
    #pragma unroll
    for (int p = 0; p < NPAIR; p++) {
        float s0, s1, y0, y1;
        unpack2(sum[p], s0, s1);
        unpack2(yy[p],  y0, y1);
        int r0 = t + (2 * p)     * RSTRIDE;
        int r1 = t + (2 * p + 1) * RSTRIDE;
        gp2[r0 * PSTRIDE + slice] = make_float2(s0, y0);
        gp2[r1 * PSTRIDE + slice] = make_float2(s1, y1);
    }
}

// ---------- Kernel C: reduce slices (4 lanes/row) + conv-sigmoid + head-sigmoid ----------
__global__ void __launch_bounds__(256) k_tail(
                       const float* __restrict__ conv_b,
                       const float* __restrict__ head_w, const float* __restrict__ head_b,
                       float* __restrict__ out)
{
    int tid = blockIdx.x * 256 + threadIdx.x;
    int row = tid >> 2;          // 4 lanes per row
    int l   = tid & 3;

    // 19 float4 chunks per row; lane l takes chunks l, l+4, ... (5,5,5,4)
    const float4* __restrict__ p = gP + row * (PSTRIDE / 2);
    float sum = 0.f, y = 0.f;
    #pragma unroll
    for (int i = l; i < PSTRIDE / 2; i += 4) {
        float4 v = __ldg(p + i);      // {sum0, y0, sum1, y1}
        sum += v.x + v.z;
        y   += v.y + v.w;
    }
    // width-4 butterfly reduce (fixed order -> deterministic)
    sum += __shfl_xor_sync(0xffffffffu, sum, 1, 4);
    y   += __shfl_xor_sync(0xffffffffu, y,   1, 4);
    sum += __shfl_xor_sync(0xffffffffu, sum, 2, 4);
    y   += __shfl_xor_sync(0xffffffffu, y,   2, 4);

    if (l == 0) {
        float z = fmaf(y, 1.f / sum, conv_b[0]);
        float f = 1.f / (1.f + expf(-z));
        float logit = fmaf(f, head_w[0], head_b[0]);
        out[row] = 1.f / (1.f + expf(-logit));
    }
}

extern "C" void kernel_launch(void* const* d_in, const int* in_sizes, int n_in,
                              void* d_out, int out_size)
{
    const float* inp  = (const float*)d_in[0];
    const float* Wfm  = (const float*)d_in[1];
    const float* bfm  = (const float*)d_in[2];
    const float* Wc1  = (const float*)d_in[3];
    const float* bc1  = (const float*)d_in[4];
    const float* Wp1  = (const float*)d_in[5];
    const float* bp1  = (const float*)d_in[6];
    const float* Wc2  = (const float*)d_in[7];
    const float* bc2  = (const float*)d_in[8];
    const float* Wp2  = (const float*)d_in[9];
    const float* bp2  = (const float*)d_in[10];
    const float* Wc3  = (const float*)d_in[11];
    const float* bc3  = (const float*)d_in[12];
    const float* rot  = (const float*)d_in[13];
    const float* ent  = (const float*)d_in[14];
    const float* cw   = (const float*)d_in[15];
    const float* cb   = (const float*)d_in[16];
    const float* hw   = (const float*)d_in[17];
    const float* hb   = (const float*)d_in[18];
    float* out = (float*)d_out;

    k_prep<<<NB / 64, 256>>>(inp, Wfm, bfm, Wc1, bc1, Wp1, bp1,
                             Wc2, bc2, Wp2, bp2, Wc3, bc3, rot, ent, cw);
    dim3 gridB(RSTRIDE / 512, NSLICE);   // 4 x 37 = 148 blocks, 16 warps each
    k_attn<<<gridB, 512>>>();
    k_tail<<<NB * 4 / 256, 256>>>(cb, hw, hb, out);
}